// round 11
// baseline (speedup 1.0000x reference)
#include <cuda_runtime.h>
#include <math.h>

#define NB 256
#define IH 144
#define IW 256
#define HR 144
#define WR 256
#define F 16
#define D 128
#define BPT 4   // batches per block (sample kernel) — proven optimum

#define FOV_HALF 0.654498469497874f   // 0.5 * 75deg in rad
#define GELU_GAMMA 1.7015043497085571f

// Scratch (no allocations allowed)
__device__ float2 g_dirq[HR * WR];     // homography coords q = d.xy / d.z
__device__ float  g_rm[NB * 12];       // rotation matrices: 9 contiguous floats
                                       // (row 2 pre-scaled by 1/128), stride 12

__device__ __forceinline__ float gelu_tanh(float x) {
    // matches jax.nn.gelu(approximate=True)
    float x3 = x * x * x;
    float inner = 0.7978845608028654f * (x + 0.044715f * x3);
    float t = tanhf(inner);
    return 0.5f * x * (1.0f + t);
}

// ---------------------------------------------------------------------------
// Kernel 1 (merged): blocks [0, HR) build the q table; blocks [HR, HR+NB)
// run the per-batch MLP -> Euler angles -> rotation matrix.
// Layer 2 split across 2 threads/neuron; projection via warp reductions.
// (R10 version — measured −2.6us on total overhead.)
// ---------------------------------------------------------------------------
__global__ void setup_kernel(const float* __restrict__ persp,
                             const float* __restrict__ W1, const float* __restrict__ b1,
                             const float* __restrict__ W2, const float* __restrict__ b2,
                             const float* __restrict__ Wp, const float* __restrict__ bp) {
    if (blockIdx.x < HR) {
        // ---- q table: d = (sinc*ax, sinc*ay, cos a); q = d.xy / cos a ----
        int w = threadIdx.x;
        int h = blockIdx.x;
        float gx = ((float)(2 * w + 1 - WR)) * (1.0f / 256.0f);
        float gy = ((float)(2 * h + 1 - HR)) * (1.0f / 256.0f);
        float ax = gx * FOV_HALF;
        float ay = gy * FOV_HALF;
        float a = sqrtf(ax * ax + ay * ay) + 1e-12f;
        float s, c;
        sincosf(a, &s, &c);
        float t = s / (a * c);          // tan(a)/a   (a < 0.75 rad, c > 0.7)
        g_dirq[h * WR + w] = make_float2(t * ax, t * ay);
        return;
    }

    // ---- MLP ----
    __shared__ float sp[F];
    __shared__ float h1[D];
    __shared__ float h2[D];
    __shared__ float part[2 * D];
    __shared__ float sang[3];

    int n = blockIdx.x - HR;
    int tid = threadIdx.x;

    if (tid < F) sp[tid] = persp[n * F + tid];
    __syncthreads();

    // layer 1: threads 0..127, one neuron each (16 MACs)
    if (tid < D) {
        float acc = b1[tid];
#pragma unroll
        for (int k = 0; k < F; k++)
            acc = fmaf(sp[k], __ldg(&W1[k * D + tid]), acc);
        h1[tid] = gelu_tanh(acc) * GELU_GAMMA;
    }
    __syncthreads();

    // layer 2: 2 threads per neuron — thread (tid&127) + half (tid>>7)
    {
        int neuron = tid & (D - 1);
        int half = tid >> 7;               // 0 or 1
        int k0 = half * (D / 2);
        float acc = 0.0f;
#pragma unroll 8
        for (int k = 0; k < D / 2; k++)
            acc = fmaf(h1[k0 + k], __ldg(&W2[(k0 + k) * D + neuron]), acc);
        part[tid] = acc;
    }
    __syncthreads();
    if (tid < D) {
        float acc2 = b2[tid] + part[tid] + part[tid + D];
        h2[tid] = gelu_tanh(acc2) * GELU_GAMMA;
    }
    __syncthreads();

    // projection: warp a (a<3) reduces angle a over 128 k's
    if (tid < 96) {
        int a = tid >> 5;            // 0..2
        int l = tid & 31;
        float acc = 0.0f;
#pragma unroll
        for (int i = 0; i < 4; i++)
            acc = fmaf(h2[l + 32 * i], __ldg(&Wp[(l + 32 * i) * 3 + a]), acc);
#pragma unroll
        for (int off = 16; off > 0; off >>= 1)
            acc += __shfl_down_sync(0xffffffffu, acc, off);
        if (l == 0) sang[a] = acc + bp[a];
    }
    __syncthreads();

    if (tid == 0) {
        float axr = sang[0], ayr = sang[1], azr = sang[2];
        float cx, sx, cy, sy, cz, sz;
        sincosf(axr, &sx, &cx);
        sincosf(ayr, &sy, &cy);
        sincosf(azr, &sz, &cz);
        // R = Rz @ Ry @ Rx ; row 2 pre-scaled by 1/128 so px = rx/rz128 + 127.5
        float* r = &g_rm[n * 12];
        r[0] = cz * cy;
        r[1] = cz * sy * sx - sz * cx;
        r[2] = cz * sy * cx + sz * sx;
        r[3] = sz * cy;
        r[4] = sz * sy * sx + cz * cx;
        r[5] = sz * sy * cx - cz * sx;
        r[6] = -sy      * 0.0078125f;
        r[7] = cy * sx  * 0.0078125f;
        r[8] = cy * cx  * 0.0078125f;
        r[9] = 0.0f; r[10] = 0.0f; r[11] = 0.0f;
    }
}

// ---------------------------------------------------------------------------
// Kernel 2: rotate rays (homography form), project, bilinear sample.
//   Exact R4 body (proven optimum): 9 SCALAR broadcast LDS per pixel-batch
//   (uniform scalar LDS is the 1-cycle fast path; wide uniform LDS measured
//   slower), straight-line predicated gathers, batch offsets as immediates.
//   grid = (HR, NB/BPT), block = 256
// ---------------------------------------------------------------------------
__global__ void __launch_bounds__(256) sample_kernel(const float* __restrict__ stim,
                                                     float* __restrict__ out) {
    __shared__ float r[BPT * 12];
    int w = threadIdx.x;
    int h = blockIdx.x;
    int nb = blockIdx.y * BPT;

    if (threadIdx.x < BPT * 12) r[threadIdx.x] = g_rm[nb * 12 + threadIdx.x];
    __syncthreads();

    float2 q = g_dirq[h * WR + w];

    const float* img = stim + (size_t)nb * (IH * IW);
    float* outp = out + ((size_t)nb * IH + h) * IW + w;

#pragma unroll
    for (int b = 0; b < BPT; b++) {
        const float* rb = &r[b * 12];
        float rx = fmaf(rb[0], q.x, fmaf(rb[1], q.y, rb[2]));
        float ry = fmaf(rb[3], q.x, fmaf(rb[4], q.y, rb[5]));
        float rz = fmaf(rb[6], q.x, fmaf(rb[7], q.y, rb[8]));  // true rz / 128

        bool safe = rz > 7.8125e-6f;                 // 0.001/128
        float inv = __fdividef(1.0f, rz);
        float px = safe ? fmaf(rx, inv, 127.5f) : 1.0e8f;
        float py = safe ? fmaf(ry, inv, 71.5f)  : 1.0e8f;

        float x0f = floorf(px);
        float y0f = floorf(py);
        float wx = px - x0f;
        float wy = py - y0f;
        int x0 = (int)x0f;
        int y0 = (int)y0f;

        bool vx0 = (unsigned)x0 < (unsigned)IW;
        bool vx1 = (unsigned)(x0 + 1) < (unsigned)IW;
        bool vy0 = (unsigned)y0 < (unsigned)IH;
        bool vy1 = (unsigned)(y0 + 1) < (unsigned)IH;

        // single base; invalid corners are predicated off — no clamping.
        int base = y0 * IW + x0 + b * (IH * IW);   // batch offset -> immediate
        float v00 = (vy0 && vx0) ? __ldg(img + base)          : 0.0f;
        float v01 = (vy0 && vx1) ? __ldg(img + base + 1)      : 0.0f;
        float v10 = (vy1 && vx0) ? __ldg(img + base + IW)     : 0.0f;
        float v11 = (vy1 && vx1) ? __ldg(img + base + IW + 1) : 0.0f;

        float top = fmaf(wx, v01 - v00, v00);
        float bot = fmaf(wx, v11 - v10, v10);
        outp[b * (IH * IW)] = fmaf(wy, bot - top, top);    // immediate offset
    }
}

// ---------------------------------------------------------------------------
extern "C" void kernel_launch(void* const* d_in, const int* in_sizes, int n_in,
                              void* d_out, int out_size) {
    const float* stimulus = (const float*)d_in[0];
    const float* persp    = (const float*)d_in[1];
    const float* W1       = (const float*)d_in[2];
    const float* b1       = (const float*)d_in[3];
    const float* W2       = (const float*)d_in[4];
    const float* b2       = (const float*)d_in[5];
    const float* Wp       = (const float*)d_in[6];
    const float* bp       = (const float*)d_in[7];
    float* out = (float*)d_out;

    setup_kernel<<<HR + NB, WR>>>(persp, W1, b1, W2, b2, Wp, bp);
    sample_kernel<<<dim3(HR, NB / BPT), 256>>>(stimulus, out);
}

// round 14
// speedup vs baseline: 1.5378x; 1.5378x over previous
#include <cuda_runtime.h>
#include <math.h>

#define NB 256
#define IH 144
#define IW 256
#define HR 144
#define WR 256
#define F 16
#define D 128
#define BPT 4   // batches per block (sample kernel) — proven optimum

#define FOV_HALF 0.654498469497874f   // 0.5 * 75deg in rad
#define GELU_GAMMA 1.7015043497085571f

// Scratch (no allocations allowed)
__device__ float2 g_dirq[HR * WR];     // homography coords q = d.xy / d.z
__device__ float  g_rm[NB * 12];       // rotation matrices: 9 contiguous floats
                                       // (row 2 pre-scaled by 1/128), stride 12

__device__ __forceinline__ float gelu_tanh(float x) {
    // matches jax.nn.gelu(approximate=True)
    float x3 = x * x * x;
    float inner = 0.7978845608028654f * (x + 0.044715f * x3);
    float t = tanhf(inner);
    return 0.5f * x * (1.0f + t);
}

// ---------------------------------------------------------------------------
// Kernel 1 (merged): blocks [0, HR) build the q table; blocks [HR, HR+NB)
// run the per-batch MLP -> Euler angles -> rotation matrix.
// Layer 2 split across 2 threads/neuron; projection via warp reductions.
// ---------------------------------------------------------------------------
__global__ void setup_kernel(const float* __restrict__ persp,
                             const float* __restrict__ W1, const float* __restrict__ b1,
                             const float* __restrict__ W2, const float* __restrict__ b2,
                             const float* __restrict__ Wp, const float* __restrict__ bp) {
    if (blockIdx.x < HR) {
        // ---- q table: d = (sinc*ax, sinc*ay, cos a); q = d.xy / cos a ----
        int w = threadIdx.x;
        int h = blockIdx.x;
        float gx = ((float)(2 * w + 1 - WR)) * (1.0f / 256.0f);
        float gy = ((float)(2 * h + 1 - HR)) * (1.0f / 256.0f);
        float ax = gx * FOV_HALF;
        float ay = gy * FOV_HALF;
        float a = sqrtf(ax * ax + ay * ay) + 1e-12f;
        float s, c;
        sincosf(a, &s, &c);
        float t = s / (a * c);          // tan(a)/a   (a < 0.75 rad, c > 0.7)
        g_dirq[h * WR + w] = make_float2(t * ax, t * ay);
        return;
    }

    // ---- MLP ----
    __shared__ float sp[F];
    __shared__ float h1[D];
    __shared__ float h2[D];
    __shared__ float part[2 * D];
    __shared__ float sang[3];

    int n = blockIdx.x - HR;
    int tid = threadIdx.x;

    if (tid < F) sp[tid] = persp[n * F + tid];
    __syncthreads();

    // layer 1: threads 0..127, one neuron each (16 MACs)
    if (tid < D) {
        float acc = b1[tid];
#pragma unroll
        for (int k = 0; k < F; k++)
            acc = fmaf(sp[k], __ldg(&W1[k * D + tid]), acc);
        h1[tid] = gelu_tanh(acc) * GELU_GAMMA;
    }
    __syncthreads();

    // layer 2: 2 threads per neuron — thread (tid&127) + half (tid>>7)
    {
        int neuron = tid & (D - 1);
        int half = tid >> 7;               // 0 or 1
        int k0 = half * (D / 2);
        float acc = 0.0f;
#pragma unroll 8
        for (int k = 0; k < D / 2; k++)
            acc = fmaf(h1[k0 + k], __ldg(&W2[(k0 + k) * D + neuron]), acc);
        part[tid] = acc;
    }
    __syncthreads();
    if (tid < D) {
        float acc2 = b2[tid] + part[tid] + part[tid + D];
        h2[tid] = gelu_tanh(acc2) * GELU_GAMMA;
    }
    __syncthreads();

    // projection: warp a (a<3) reduces angle a over 128 k's
    if (tid < 96) {
        int a = tid >> 5;            // 0..2
        int l = tid & 31;
        float acc = 0.0f;
#pragma unroll
        for (int i = 0; i < 4; i++)
            acc = fmaf(h2[l + 32 * i], __ldg(&Wp[(l + 32 * i) * 3 + a]), acc);
#pragma unroll
        for (int off = 16; off > 0; off >>= 1)
            acc += __shfl_down_sync(0xffffffffu, acc, off);
        if (l == 0) sang[a] = acc + bp[a];
    }
    __syncthreads();

    if (tid == 0) {
        float axr = sang[0], ayr = sang[1], azr = sang[2];
        float cx, sx, cy, sy, cz, sz;
        sincosf(axr, &sx, &cx);
        sincosf(ayr, &sy, &cy);
        sincosf(azr, &sz, &cz);
        // R = Rz @ Ry @ Rx ; row 2 pre-scaled by 1/128 so px = rx/rz128 + 127.5
        float* r = &g_rm[n * 12];
        r[0] = cz * cy;
        r[1] = cz * sy * sx - sz * cx;
        r[2] = cz * sy * cx + sz * sx;
        r[3] = sz * cy;
        r[4] = sz * sy * sx + cz * cx;
        r[5] = sz * sy * cx - cz * sx;
        r[6] = -sy      * 0.0078125f;
        r[7] = cy * sx  * 0.0078125f;
        r[8] = cy * cx  * 0.0078125f;
        r[9] = 0.0f; r[10] = 0.0f; r[11] = 0.0f;
    }
}

// ---------------------------------------------------------------------------
// Kernel 2: rotate rays (homography form), project, bilinear sample.
//   R10 body (best measured: 27.46us): coefficients via 4x LDS.64 + 1 LDS.32
//   from padded stride-12 layout; straight-line predicated gathers; batch
//   offsets as compile-time immediates.
//   grid = (HR, NB/BPT), block = 256
// ---------------------------------------------------------------------------
__global__ void __launch_bounds__(256) sample_kernel(const float* __restrict__ stim,
                                                     float* __restrict__ out) {
    __shared__ float r[BPT * 12];
    int w = threadIdx.x;
    int h = blockIdx.x;
    int nb = blockIdx.y * BPT;

    if (threadIdx.x < BPT * 12) r[threadIdx.x] = g_rm[nb * 12 + threadIdx.x];
    __syncthreads();

    float2 q = g_dirq[h * WR + w];

    const float* img = stim + (size_t)nb * (IH * IW);
    float* outp = out + ((size_t)nb * IH + h) * IW + w;

#pragma unroll
    for (int b = 0; b < BPT; b++) {
        const float2* rp = (const float2*)&r[b * 12];
        float2 c0 = rp[0];              // r0 r1
        float2 c1 = rp[1];              // r2 r3
        float2 c2 = rp[2];              // r4 r5
        float2 c3 = rp[3];              // r6 r7  (prescaled 1/128)
        float  c8 = r[b * 12 + 8];      // r8     (prescaled 1/128)

        float rx = fmaf(c0.x, q.x, fmaf(c0.y, q.y, c1.x));
        float ry = fmaf(c1.y, q.x, fmaf(c2.x, q.y, c2.y));
        float rz = fmaf(c3.x, q.x, fmaf(c3.y, q.y, c8));   // true rz / 128

        bool safe = rz > 7.8125e-6f;                 // 0.001/128
        float inv = __fdividef(1.0f, rz);
        float px = safe ? fmaf(rx, inv, 127.5f) : 1.0e8f;
        float py = safe ? fmaf(ry, inv, 71.5f)  : 1.0e8f;

        float x0f = floorf(px);
        float y0f = floorf(py);
        float wx = px - x0f;
        float wy = py - y0f;
        int x0 = (int)x0f;
        int y0 = (int)y0f;

        bool vx0 = (unsigned)x0 < (unsigned)IW;
        bool vx1 = (unsigned)(x0 + 1) < (unsigned)IW;
        bool vy0 = (unsigned)y0 < (unsigned)IH;
        bool vy1 = (unsigned)(y0 + 1) < (unsigned)IH;

        // single base; invalid corners are predicated off — no clamping.
        int base = y0 * IW + x0 + b * (IH * IW);
        float v00 = (vy0 && vx0) ? __ldg(img + base)          : 0.0f;
        float v01 = (vy0 && vx1) ? __ldg(img + base + 1)      : 0.0f;
        float v10 = (vy1 && vx0) ? __ldg(img + base + IW)     : 0.0f;
        float v11 = (vy1 && vx1) ? __ldg(img + base + IW + 1) : 0.0f;

        float top = fmaf(wx, v01 - v00, v00);
        float bot = fmaf(wx, v11 - v10, v10);
        outp[b * (IH * IW)] = fmaf(wy, bot - top, top);
    }
}

// ---------------------------------------------------------------------------
extern "C" void kernel_launch(void* const* d_in, const int* in_sizes, int n_in,
                              void* d_out, int out_size) {
    const float* stimulus = (const float*)d_in[0];
    const float* persp    = (const float*)d_in[1];
    const float* W1       = (const float*)d_in[2];
    const float* b1       = (const float*)d_in[3];
    const float* W2       = (const float*)d_in[4];
    const float* b2       = (const float*)d_in[5];
    const float* Wp       = (const float*)d_in[6];
    const float* bp       = (const float*)d_in[7];
    float* out = (float*)d_out;

    setup_kernel<<<HR + NB, WR>>>(persp, W1, b1, W2, b2, Wp, bp);
    sample_kernel<<<dim3(HR, NB / BPT), 256>>>(stimulus, out);
}

// round 15
// speedup vs baseline: 1.6161x; 1.0509x over previous
#include <cuda_runtime.h>
#include <math.h>

#define NB 256
#define IH 144
#define IW 256
#define HR 144
#define WR 256
#define F 16
#define D 128
#define BPT 4   // batches per block (sample kernel) — proven optimum

#define FOV_HALF 0.654498469497874f   // 0.5 * 75deg in rad
#define GELU_GAMMA 1.7015043497085571f

// Scratch (no allocations allowed)
__device__ float2 g_dirq[HR * WR];     // homography coords q = d.xy / d.z
__device__ float  g_rm[NB * 12];       // rotation matrices: 9 contiguous floats
                                       // (row 2 pre-scaled by 1/128), stride 12

__device__ __forceinline__ float gelu_tanh(float x) {
    // matches jax.nn.gelu(approximate=True)
    float x3 = x * x * x;
    float inner = 0.7978845608028654f * (x + 0.044715f * x3);
    float t = tanhf(inner);
    return 0.5f * x * (1.0f + t);
}

// ---------------------------------------------------------------------------
// Kernel 1 (merged): blocks [0, HR) build the q table; blocks [HR, HR+NB)
// run the per-batch MLP -> Euler angles -> rotation matrix.
// Layer 2 split across 2 threads/neuron; projection via warp reductions.
// ---------------------------------------------------------------------------
__global__ void setup_kernel(const float* __restrict__ persp,
                             const float* __restrict__ W1, const float* __restrict__ b1,
                             const float* __restrict__ W2, const float* __restrict__ b2,
                             const float* __restrict__ Wp, const float* __restrict__ bp) {
    if (blockIdx.x < HR) {
        // ---- q table: d = (sinc*ax, sinc*ay, cos a); q = d.xy / cos a ----
        int w = threadIdx.x;
        int h = blockIdx.x;
        float gx = ((float)(2 * w + 1 - WR)) * (1.0f / 256.0f);
        float gy = ((float)(2 * h + 1 - HR)) * (1.0f / 256.0f);
        float ax = gx * FOV_HALF;
        float ay = gy * FOV_HALF;
        float a = sqrtf(ax * ax + ay * ay) + 1e-12f;
        float s, c;
        sincosf(a, &s, &c);
        float t = s / (a * c);          // tan(a)/a   (a < 0.75 rad, c > 0.7)
        g_dirq[h * WR + w] = make_float2(t * ax, t * ay);
        return;
    }

    // ---- MLP ----
    __shared__ float sp[F];
    __shared__ float h1[D];
    __shared__ float h2[D];
    __shared__ float part[2 * D];
    __shared__ float sang[3];

    int n = blockIdx.x - HR;
    int tid = threadIdx.x;

    if (tid < F) sp[tid] = persp[n * F + tid];
    __syncthreads();

    // layer 1: threads 0..127, one neuron each (16 MACs)
    if (tid < D) {
        float acc = b1[tid];
#pragma unroll
        for (int k = 0; k < F; k++)
            acc = fmaf(sp[k], __ldg(&W1[k * D + tid]), acc);
        h1[tid] = gelu_tanh(acc) * GELU_GAMMA;
    }
    __syncthreads();

    // layer 2: 2 threads per neuron — thread (tid&127) + half (tid>>7)
    {
        int neuron = tid & (D - 1);
        int half = tid >> 7;               // 0 or 1
        int k0 = half * (D / 2);
        float acc = 0.0f;
#pragma unroll 8
        for (int k = 0; k < D / 2; k++)
            acc = fmaf(h1[k0 + k], __ldg(&W2[(k0 + k) * D + neuron]), acc);
        part[tid] = acc;
    }
    __syncthreads();
    if (tid < D) {
        float acc2 = b2[tid] + part[tid] + part[tid + D];
        h2[tid] = gelu_tanh(acc2) * GELU_GAMMA;
    }
    __syncthreads();

    // projection: warp a (a<3) reduces angle a over 128 k's
    if (tid < 96) {
        int a = tid >> 5;            // 0..2
        int l = tid & 31;
        float acc = 0.0f;
#pragma unroll
        for (int i = 0; i < 4; i++)
            acc = fmaf(h2[l + 32 * i], __ldg(&Wp[(l + 32 * i) * 3 + a]), acc);
#pragma unroll
        for (int off = 16; off > 0; off >>= 1)
            acc += __shfl_down_sync(0xffffffffu, acc, off);
        if (l == 0) sang[a] = acc + bp[a];
    }
    __syncthreads();

    if (tid == 0) {
        float axr = sang[0], ayr = sang[1], azr = sang[2];
        float cx, sx, cy, sy, cz, sz;
        sincosf(axr, &sx, &cx);
        sincosf(ayr, &sy, &cy);
        sincosf(azr, &sz, &cz);
        // R = Rz @ Ry @ Rx ; row 2 pre-scaled by 1/128 so px = rx/rz128 + 127.5
        float* r = &g_rm[n * 12];
        r[0] = cz * cy;
        r[1] = cz * sy * sx - sz * cx;
        r[2] = cz * sy * cx + sz * sx;
        r[3] = sz * cy;
        r[4] = sz * sy * sx + cz * cx;
        r[5] = sz * sy * cx - cz * sx;
        r[6] = -sy      * 0.0078125f;
        r[7] = cy * sx  * 0.0078125f;
        r[8] = cy * cx  * 0.0078125f;
        r[9] = 0.0f; r[10] = 0.0f; r[11] = 0.0f;
    }
}

// ---------------------------------------------------------------------------
// Kernel 2: rotate rays (homography form), project, bilinear sample.
//   Best-evidenced body: 9 SCALAR broadcast LDS per pixel-batch (uniform
//   scalar LDS = 1-cycle crossbar fast path; wide uniform LDS measured
//   slower), straight-line predicated gathers, immediate batch offsets.
//   New: unsafe-ray handling via a single fmaxf clamp on rz — out-of-range
//   rays still predicate off all 4 corners (|rx| or |ry| >= 0.7 when
//   r_true_z <= 0.001, so px or py lands ~6e4 off-image), removing
//   1 FSETP + 2 FSEL from the critical path into the RCP.
//   grid = (HR, NB/BPT), block = 256
// ---------------------------------------------------------------------------
__global__ void __launch_bounds__(256) sample_kernel(const float* __restrict__ stim,
                                                     float* __restrict__ out) {
    __shared__ float r[BPT * 12];
    int w = threadIdx.x;
    int h = blockIdx.x;
    int nb = blockIdx.y * BPT;

    if (threadIdx.x < BPT * 12) r[threadIdx.x] = g_rm[nb * 12 + threadIdx.x];
    __syncthreads();

    float2 q = g_dirq[h * WR + w];

    const float* img = stim + (size_t)nb * (IH * IW);
    float* outp = out + ((size_t)nb * IH + h) * IW + w;

#pragma unroll
    for (int b = 0; b < BPT; b++) {
        const float* rb = &r[b * 12];
        float rx = fmaf(rb[0], q.x, fmaf(rb[1], q.y, rb[2]));
        float ry = fmaf(rb[3], q.x, fmaf(rb[4], q.y, rb[5]));
        float rz = fmaf(rb[6], q.x, fmaf(rb[7], q.y, rb[8]));  // true rz / 128

        // clamp replaces the safe-select: unsafe rays project far off-image
        float rzc = fmaxf(rz, 7.8125e-6f);           // 0.001/128
        float inv = __fdividef(1.0f, rzc);
        float px = fmaf(rx, inv, 127.5f);
        float py = fmaf(ry, inv, 71.5f);

        float x0f = floorf(px);
        float y0f = floorf(py);
        float wx = px - x0f;
        float wy = py - y0f;
        int x0 = (int)x0f;
        int y0 = (int)y0f;

        bool vx0 = (unsigned)x0 < (unsigned)IW;
        bool vx1 = (unsigned)(x0 + 1) < (unsigned)IW;
        bool vy0 = (unsigned)y0 < (unsigned)IH;
        bool vy1 = (unsigned)(y0 + 1) < (unsigned)IH;

        // single base; invalid corners are predicated off — no clamping.
        int base = y0 * IW + x0 + b * (IH * IW);   // batch offset -> immediate
        float v00 = (vy0 && vx0) ? __ldg(img + base)          : 0.0f;
        float v01 = (vy0 && vx1) ? __ldg(img + base + 1)      : 0.0f;
        float v10 = (vy1 && vx0) ? __ldg(img + base + IW)     : 0.0f;
        float v11 = (vy1 && vx1) ? __ldg(img + base + IW + 1) : 0.0f;

        float top = fmaf(wx, v01 - v00, v00);
        float bot = fmaf(wx, v11 - v10, v10);
        outp[b * (IH * IW)] = fmaf(wy, bot - top, top);    // immediate offset
    }
}

// ---------------------------------------------------------------------------
extern "C" void kernel_launch(void* const* d_in, const int* in_sizes, int n_in,
                              void* d_out, int out_size) {
    const float* stimulus = (const float*)d_in[0];
    const float* persp    = (const float*)d_in[1];
    const float* W1       = (const float*)d_in[2];
    const float* b1       = (const float*)d_in[3];
    const float* W2       = (const float*)d_in[4];
    const float* b2       = (const float*)d_in[5];
    const float* Wp       = (const float*)d_in[6];
    const float* bp       = (const float*)d_in[7];
    float* out = (float*)d_out;

    setup_kernel<<<HR + NB, WR>>>(persp, W1, b1, W2, b2, Wp, bp);
    sample_kernel<<<dim3(HR, NB / BPT), 256>>>(stimulus, out);
}